// round 9
// baseline (speedup 1.0000x reference)
#include <cuda_runtime.h>
#include <cuda_fp16.h>
#include <stdint.h>

#define U_NODES 100000
#define I_NODES 50000
#define N_NODES 150000
#define H 64
#define UH (U_NODES * H)       // 6,400,000
#define IH (I_NODES * H)       // 3,200,000
#define NH (N_NODES * H)       // 9,600,000
#define E_IN 2000000
#define E_DIR 4000000

#define SCAN_BLK 1024
#define N_SCAN_BLOCKS ((N_NODES + SCAN_BLK - 1) / SCAN_BLK)   // 147

// ---------------- scratch (device globals; no runtime allocation) ------------
__device__ __align__(16) float  d_deg[N_NODES];
__device__ __align__(16) float  d_dinv[N_NODES];
__device__ __align__(16) int    d_cnt[N_NODES];
__device__ __align__(16) int    d_rowptr[N_NODES + 1];
__device__ __align__(16) int    d_wp[N_NODES];
__device__ __align__(16) int    d_partials[N_SCAN_BLOCKS];
__device__ __align__(16) int2   d_cw[E_DIR];      // packed (col, w bits)
__device__ __align__(16) __half d_e0[NH];         // fp16 ping
__device__ __align__(16) __half d_e1[NH];         // fp16 pong
__device__ __align__(16) float  d_acc[NH];        // fp32 accumulator
__device__ int d_is64;

// ---------------- dtype-robust index read ------------------------------------
// JAX default config downcasts int64 -> int32; edge arrays may be either.
__global__ void detect_kernel(const void* __restrict__ p) {
    if (blockIdx.x == 0 && threadIdx.x == 0) {
        const long long* q = (const long long*)p;
        int is64 = 1;
        for (int i = 0; i < 256; i++) {
            long long v = q[i];
            if (v < 0 || v >= N_NODES) { is64 = 0; break; }
        }
        d_is64 = is64;
    }
}

__device__ __forceinline__ int get_idx(const void* __restrict__ p, int k) {
    if (d_is64) return (int)((const long long*)p)[k];
    return ((const int*)p)[k];
}

// ---------------- build phase -------------------------------------------------

__global__ void zero_kernel() {
    int i = blockIdx.x * blockDim.x + threadIdx.x;
    if (i < N_NODES) { d_deg[i] = 0.0f; d_cnt[i] = 0; }
}

__global__ void deg_kernel(const void* __restrict__ eu,
                           const void* __restrict__ ei,
                           const float* __restrict__ ev) {
    int k = blockIdx.x * blockDim.x + threadIdx.x;
    if (k >= E_IN) return;
    int u  = get_idx(eu, k);
    int it = get_idx(ei, k);
    if ((unsigned)u >= U_NODES || (unsigned)it >= I_NODES) return;  // safety
    it += U_NODES;
    float v = ev[k];
    atomicAdd(&d_deg[u], v);
    atomicAdd(&d_deg[it], v);
    atomicAdd(&d_cnt[u], 1);
    atomicAdd(&d_cnt[it], 1);
}

__global__ void dinv_kernel() {
    int i = blockIdx.x * blockDim.x + threadIdx.x;
    if (i >= N_NODES) return;
    float dg = d_deg[i];
    d_dinv[i] = (dg > 0.0f) ? rsqrtf(fmaxf(dg, 1e-12f)) : 0.0f;
}

__global__ void scan1_kernel() {
    __shared__ int sh[SCAN_BLK];
    int t = threadIdx.x;
    int idx = blockIdx.x * SCAN_BLK + t;
    int v = (idx < N_NODES) ? d_cnt[idx] : 0;
    sh[t] = v;
    __syncthreads();
    for (int off = 1; off < SCAN_BLK; off <<= 1) {
        int x = (t >= off) ? sh[t - off] : 0;
        __syncthreads();
        sh[t] += x;
        __syncthreads();
    }
    if (idx < N_NODES) d_rowptr[idx] = sh[t] - v;   // block-local exclusive
    if (t == SCAN_BLK - 1) d_partials[blockIdx.x] = sh[t];
}

__global__ void scan2_kernel() {
    if (blockIdx.x == 0 && threadIdx.x == 0) {
        int s = 0;
        for (int i = 0; i < N_SCAN_BLOCKS; i++) {
            int v = d_partials[i];
            d_partials[i] = s;
            s += v;
        }
    }
}

__global__ void scan3_kernel() {
    int idx = blockIdx.x * blockDim.x + threadIdx.x;
    if (idx < N_NODES) {
        int rp = d_rowptr[idx] + d_partials[idx >> 10];
        d_rowptr[idx] = rp;
        d_wp[idx] = rp;
    }
    if (idx == 0) d_rowptr[N_NODES] = E_DIR;
}

__global__ void scatter_kernel(const void* __restrict__ eu,
                               const void* __restrict__ ei,
                               const float* __restrict__ ev) {
    int k = blockIdx.x * blockDim.x + threadIdx.x;
    if (k >= E_IN) return;
    int u  = get_idx(eu, k);
    int it = get_idx(ei, k);
    if ((unsigned)u >= U_NODES || (unsigned)it >= I_NODES) return;  // safety
    it += U_NODES;
    float v = ev[k];
    float w = d_dinv[u] * v * d_dinv[it];   // symmetric weight
    int wb = __float_as_int(w);
    int p0 = atomicAdd(&d_wp[u], 1);
    d_cw[p0] = make_int2(it, wb);
    int p1 = atomicAdd(&d_wp[it], 1);
    d_cw[p1] = make_int2(u, wb);
}

// e0 = fp16(emb); acc = fp32(emb)
__global__ void init_e_kernel(const float* __restrict__ emb_u,
                              const float* __restrict__ emb_i) {
    int i = blockIdx.x * blockDim.x + threadIdx.x;
    if (i >= NH) return;
    float v = (i < UH) ? emb_u[i] : emb_i[i - UH];
    d_e0[i] = __float2half(v);
    d_acc[i] = v;
}

// ---------------- propagation layers ------------------------------------------
// R4-proven structure, fp16 storage: one warp per destination row; lane l holds
// dims [2l, 2l+1]. Each edge: one broadcast int2 (col,w) + one whole-warp
// coalesced 128-byte row gather (each lane one __half2). fp32 accumulate,
// in-kernel fp32 acc RMW. Unrolled x4.

#define GATHER(OFF)                                                            \
    {                                                                          \
        int2 cw = d_cw[j + (OFF)];                                             \
        float w = __int_as_float(cw.y);                                        \
        __half2 h = *(const __half2*)(ein + ((size_t)cw.x << 6) + base);       \
        float2 f = __half22float2(h);                                          \
        sum.x += w * f.x;                                                      \
        sum.y += w * f.y;                                                      \
    }

__global__ void layer_kernel(int flip) {
    const __half* __restrict__ ein  = flip ? d_e1 : d_e0;
    __half*       __restrict__ eout = flip ? d_e0 : d_e1;
    int warp = (blockIdx.x * blockDim.x + threadIdx.x) >> 5;
    int lane = threadIdx.x & 31;
    if (warp >= N_NODES) return;
    int s = d_rowptr[warp];
    int e = d_rowptr[warp + 1];
    float2 sum = make_float2(0.0f, 0.0f);
    int base = lane * 2;
    int j = s;
    for (; j + 3 < e; j += 4) {
        GATHER(0) GATHER(1) GATHER(2) GATHER(3)
    }
    for (; j < e; j++) { GATHER(0) }
    size_t o = ((size_t)warp << 6) + base;
    *(__half2*)(eout + o) = __floats2half2_rn(sum.x, sum.y);
    float2* ap = (float2*)(d_acc + o);
    float2 a = *ap;
    a.x += sum.x;
    a.y += sum.y;
    *ap = a;
}

// ---------------- epilogue -----------------------------------------------------
// out = [acc_users/25 | emb_users | acc_items/25 | emb_items]
__global__ void final_kernel(const float* __restrict__ emb_u,
                             const float* __restrict__ emb_i,
                             float* __restrict__ out, int out_n) {
    const float sc = 1.0f / 25.0f;   // alpha * 1/(L+1) = 1/5 * 1/5
    int i = blockIdx.x * blockDim.x + threadIdx.x;
    if (i >= out_n) return;
    float v;
    if (i < UH)                   v = d_acc[i] * sc;
    else if (i < 2 * UH)          v = emb_u[i - UH];
    else if (i < 2 * UH + IH)     v = d_acc[UH + (i - 2 * UH)] * sc;
    else if (i < 2 * UH + 2 * IH) v = emb_i[i - 2 * UH - IH];
    else                          v = 0.0f;
    out[i] = v;
}

// ---------------- launch ------------------------------------------------------

extern "C" void kernel_launch(void* const* d_in, const int* in_sizes, int n_in,
                              void* d_out, int out_size) {
    const float* emb_u = (const float*)d_in[0];
    const float* emb_i = (const float*)d_in[1];
    const void*  eu    = d_in[2];
    const void*  ei    = d_in[3];
    const float* ev    = (const float*)d_in[4];
    float* out = (float*)d_out;

    const int TB = 256;
    int gb_nodes = (N_NODES + TB - 1) / TB;
    int gb_edges = (E_IN + TB - 1) / TB;
    int gb_nh    = (NH + TB - 1) / TB;
    int gb_out   = (out_size + TB - 1) / TB;

    detect_kernel<<<1, 32>>>(eu);
    zero_kernel<<<gb_nodes, TB>>>();
    deg_kernel<<<gb_edges, TB>>>(eu, ei, ev);
    dinv_kernel<<<gb_nodes, TB>>>();
    scan1_kernel<<<N_SCAN_BLOCKS, SCAN_BLK>>>();
    scan2_kernel<<<1, 32>>>();
    scan3_kernel<<<gb_nodes, TB>>>();
    scatter_kernel<<<gb_edges, TB>>>(eu, ei, ev);
    init_e_kernel<<<gb_nh, TB>>>(emb_u, emb_i);

    int layer_blocks = (N_NODES * 32 + TB - 1) / TB;   // warp per row
    layer_kernel<<<layer_blocks, TB>>>(0);   // e0 -> e1
    layer_kernel<<<layer_blocks, TB>>>(1);   // e1 -> e0
    layer_kernel<<<layer_blocks, TB>>>(0);   // e0 -> e1
    layer_kernel<<<layer_blocks, TB>>>(1);   // e1 -> e0

    final_kernel<<<gb_out, TB>>>(emb_u, emb_i, out, out_size);
}

// round 10
// speedup vs baseline: 1.3549x; 1.3549x over previous
#include <cuda_runtime.h>
#include <stdint.h>

#define U_NODES 100000
#define I_NODES 50000
#define N_NODES 150000
#define H 64
#define UH (U_NODES * H)       // 6,400,000
#define IH (I_NODES * H)       // 3,200,000
#define NH (N_NODES * H)       // 9,600,000
#define E_IN 2000000
#define E_DIR 4000000

#define SCAN_BLK 1024
#define N_SCAN_BLOCKS ((N_NODES + SCAN_BLK - 1) / SCAN_BLK)   // 147

// ---------------- scratch (device globals; no runtime allocation) ------------
__device__ __align__(16) float d_deg[N_NODES];
__device__ __align__(16) float d_dinv[N_NODES];
__device__ __align__(16) int   d_cnt[N_NODES];
__device__ __align__(16) int   d_rowptr[N_NODES + 1];
__device__ __align__(16) int   d_wp[N_NODES];
__device__ __align__(16) int   d_partials[N_SCAN_BLOCKS];
__device__ __align__(16) int   d_col[E_DIR];
__device__ __align__(16) float d_w[E_DIR];
__device__ __align__(16) float d_e0[NH];
__device__ __align__(16) float d_e1[NH];
__device__ __align__(16) float d_acc[NH];
__device__ int d_is64;

// ---------------- dtype-robust index read ------------------------------------
// JAX default config downcasts int64 -> int32; edge arrays may be either.
__global__ void detect_kernel(const void* __restrict__ p) {
    if (blockIdx.x == 0 && threadIdx.x == 0) {
        const long long* q = (const long long*)p;
        int is64 = 1;
        for (int i = 0; i < 256; i++) {
            long long v = q[i];
            if (v < 0 || v >= N_NODES) { is64 = 0; break; }
        }
        d_is64 = is64;
    }
}

__device__ __forceinline__ int get_idx(const void* __restrict__ p, int k) {
    if (d_is64) return (int)((const long long*)p)[k];
    return ((const int*)p)[k];
}

// ---------------- build phase -------------------------------------------------

__global__ void zero_kernel() {
    int i = blockIdx.x * blockDim.x + threadIdx.x;
    if (i < N_NODES) { d_deg[i] = 0.0f; d_cnt[i] = 0; }
}

__global__ void deg_kernel(const void* __restrict__ eu,
                           const void* __restrict__ ei,
                           const float* __restrict__ ev) {
    int k = blockIdx.x * blockDim.x + threadIdx.x;
    if (k >= E_IN) return;
    int u  = get_idx(eu, k);
    int it = get_idx(ei, k);
    if ((unsigned)u >= U_NODES || (unsigned)it >= I_NODES) return;  // safety
    it += U_NODES;
    float v = ev[k];
    atomicAdd(&d_deg[u], v);
    atomicAdd(&d_deg[it], v);
    atomicAdd(&d_cnt[u], 1);
    atomicAdd(&d_cnt[it], 1);
}

__global__ void dinv_kernel() {
    int i = blockIdx.x * blockDim.x + threadIdx.x;
    if (i >= N_NODES) return;
    float dg = d_deg[i];
    d_dinv[i] = (dg > 0.0f) ? rsqrtf(fmaxf(dg, 1e-12f)) : 0.0f;
}

__global__ void scan1_kernel() {
    __shared__ int sh[SCAN_BLK];
    int t = threadIdx.x;
    int idx = blockIdx.x * SCAN_BLK + t;
    int v = (idx < N_NODES) ? d_cnt[idx] : 0;
    sh[t] = v;
    __syncthreads();
    for (int off = 1; off < SCAN_BLK; off <<= 1) {
        int x = (t >= off) ? sh[t - off] : 0;
        __syncthreads();
        sh[t] += x;
        __syncthreads();
    }
    if (idx < N_NODES) d_rowptr[idx] = sh[t] - v;   // block-local exclusive
    if (t == SCAN_BLK - 1) d_partials[blockIdx.x] = sh[t];
}

__global__ void scan2_kernel() {
    if (blockIdx.x == 0 && threadIdx.x == 0) {
        int s = 0;
        for (int i = 0; i < N_SCAN_BLOCKS; i++) {
            int v = d_partials[i];
            d_partials[i] = s;
            s += v;
        }
    }
}

__global__ void scan3_kernel() {
    int idx = blockIdx.x * blockDim.x + threadIdx.x;
    if (idx < N_NODES) {
        int rp = d_rowptr[idx] + d_partials[idx >> 10];
        d_rowptr[idx] = rp;
        d_wp[idx] = rp;
    }
    if (idx == 0) d_rowptr[N_NODES] = E_DIR;
}

__global__ void scatter_kernel(const void* __restrict__ eu,
                               const void* __restrict__ ei,
                               const float* __restrict__ ev) {
    int k = blockIdx.x * blockDim.x + threadIdx.x;
    if (k >= E_IN) return;
    int u  = get_idx(eu, k);
    int it = get_idx(ei, k);
    if ((unsigned)u >= U_NODES || (unsigned)it >= I_NODES) return;  // safety
    it += U_NODES;
    float v = ev[k];
    float w = d_dinv[u] * v * d_dinv[it];   // symmetric weight
    int p0 = atomicAdd(&d_wp[u], 1);
    d_col[p0] = it;
    d_w[p0]   = w;
    int p1 = atomicAdd(&d_wp[it], 1);
    d_col[p1] = u;
    d_w[p1]   = w;
}

// e0 = acc = concat(emb_users, emb_items), float4 vectorized (UH % 4 == 0)
__global__ void init_e_kernel(const float* __restrict__ emb_u,
                              const float* __restrict__ emb_i) {
    int q = blockIdx.x * blockDim.x + threadIdx.x;   // float4 index
    if (q >= NH / 4) return;
    int i = q * 4;
    float4 v = (i < UH) ? ((const float4*)emb_u)[q]
                        : ((const float4*)emb_i)[q - UH / 4];
    ((float4*)d_e0)[q]  = v;
    ((float4*)d_acc)[q] = v;
}

// ---------------- propagation layers ------------------------------------------
// EXACT R4 champion structure: one warp per row, lane l holds dims [2l,2l+1],
// per edge: scalar col + w broadcast loads + whole-warp float2 row gather,
// unrolled x4, fp32 acc RMW in-kernel. TB=128.

__global__ void layer_kernel(int flip) {
    const float* __restrict__ ein  = flip ? d_e1 : d_e0;
    float*       __restrict__ eout = flip ? d_e0 : d_e1;
    int warp = (blockIdx.x * blockDim.x + threadIdx.x) >> 5;
    int lane = threadIdx.x & 31;
    if (warp >= N_NODES) return;
    int s = d_rowptr[warp];
    int e = d_rowptr[warp + 1];
    float2 sum = make_float2(0.0f, 0.0f);
    int base = lane * 2;
    int j = s;
    for (; j + 3 < e; j += 4) {          // unrolled x4 for MLP
        int   c0 = d_col[j],     c1 = d_col[j + 1];
        int   c2 = d_col[j + 2], c3 = d_col[j + 3];
        float w0 = d_w[j],       w1 = d_w[j + 1];
        float w2 = d_w[j + 2],   w3 = d_w[j + 3];
        float2 v0 = *(const float2*)(ein + (size_t)c0 * H + base);
        float2 v1 = *(const float2*)(ein + (size_t)c1 * H + base);
        float2 v2 = *(const float2*)(ein + (size_t)c2 * H + base);
        float2 v3 = *(const float2*)(ein + (size_t)c3 * H + base);
        sum.x += w0 * v0.x + w1 * v1.x + w2 * v2.x + w3 * v3.x;
        sum.y += w0 * v0.y + w1 * v1.y + w2 * v2.y + w3 * v3.y;
    }
    for (; j < e; j++) {
        int c = d_col[j];
        float w = d_w[j];
        float2 v = *(const float2*)(ein + (size_t)c * H + base);
        sum.x += w * v.x;
        sum.y += w * v.y;
    }
    size_t o = (size_t)warp * H + base;
    *(float2*)(eout + o) = sum;
    float2* ap = (float2*)(d_acc + o);
    float2 a = *ap;
    a.x += sum.x;
    a.y += sum.y;
    *ap = a;
}

// ---------------- epilogue -----------------------------------------------------
// out = [acc_users/25 | emb_users | acc_items/25 | emb_items], float4 path.
// Section boundaries (UH, 2UH, 2UH+IH, 2UH+2IH) are all multiples of 4.
__global__ void final_kernel(const float* __restrict__ emb_u,
                             const float* __restrict__ emb_i,
                             float* __restrict__ out, int out_n) {
    const float sc = 1.0f / 25.0f;   // alpha * 1/(L+1) = 1/5 * 1/5
    int q = blockIdx.x * blockDim.x + threadIdx.x;   // float4 index
    int i = q * 4;
    if (i >= out_n) return;
    if (i + 3 < out_n && i + 4 <= 2 * UH + 2 * IH) {
        float4 v;
        if (i < UH) {
            float4 a = ((const float4*)d_acc)[q];
            v = make_float4(a.x * sc, a.y * sc, a.z * sc, a.w * sc);
        } else if (i < 2 * UH) {
            v = ((const float4*)emb_u)[q - UH / 4];
        } else if (i < 2 * UH + IH) {
            float4 a = ((const float4*)d_acc)[UH / 4 + (q - 2 * UH / 4)];
            v = make_float4(a.x * sc, a.y * sc, a.z * sc, a.w * sc);
        } else {
            v = ((const float4*)emb_i)[q - (2 * UH + IH) / 4];
        }
        ((float4*)out)[q] = v;
    } else {
        for (int t = i; t < out_n && t < i + 4; t++) {
            float v;
            if (t < UH)                   v = d_acc[t] * sc;
            else if (t < 2 * UH)          v = emb_u[t - UH];
            else if (t < 2 * UH + IH)     v = d_acc[UH + (t - 2 * UH)] * sc;
            else if (t < 2 * UH + 2 * IH) v = emb_i[t - 2 * UH - IH];
            else                          v = 0.0f;
            out[t] = v;
        }
    }
}

// ---------------- launch ------------------------------------------------------

extern "C" void kernel_launch(void* const* d_in, const int* in_sizes, int n_in,
                              void* d_out, int out_size) {
    const float* emb_u = (const float*)d_in[0];
    const float* emb_i = (const float*)d_in[1];
    const void*  eu    = d_in[2];
    const void*  ei    = d_in[3];
    const float* ev    = (const float*)d_in[4];
    float* out = (float*)d_out;

    const int TB = 256;
    int gb_nodes = (N_NODES + TB - 1) / TB;
    int gb_edges = (E_IN + TB - 1) / TB;
    int gb_nh4   = (NH / 4 + TB - 1) / TB;
    int gb_out4  = (out_size / 4 + TB) / TB;

    detect_kernel<<<1, 32>>>(eu);
    zero_kernel<<<gb_nodes, TB>>>();
    deg_kernel<<<gb_edges, TB>>>(eu, ei, ev);
    dinv_kernel<<<gb_nodes, TB>>>();
    scan1_kernel<<<N_SCAN_BLOCKS, SCAN_BLK>>>();
    scan2_kernel<<<1, 32>>>();
    scan3_kernel<<<gb_nodes, TB>>>();
    scatter_kernel<<<gb_edges, TB>>>(eu, ei, ev);
    init_e_kernel<<<gb_nh4, TB>>>(emb_u, emb_i);

    // warp per row, TB=128 (4 warps/block) for finer scheduling granularity
    const int LTB = 128;
    int layer_blocks = (N_NODES * 32 + LTB - 1) / LTB;
    layer_kernel<<<layer_blocks, LTB>>>(0);   // e0 -> e1
    layer_kernel<<<layer_blocks, LTB>>>(1);   // e1 -> e0
    layer_kernel<<<layer_blocks, LTB>>>(0);   // e0 -> e1
    layer_kernel<<<layer_blocks, LTB>>>(1);   // e1 -> e0

    final_kernel<<<gb_out4, TB>>>(emb_u, emb_i, out, out_size);
}

// round 11
// speedup vs baseline: 1.3599x; 1.0037x over previous
#include <cuda_runtime.h>
#include <stdint.h>

#define U_NODES 100000
#define I_NODES 50000
#define N_NODES 150000
#define H 64
#define UH (U_NODES * H)       // 6,400,000
#define IH (I_NODES * H)       // 3,200,000
#define NH (N_NODES * H)       // 9,600,000
#define E_IN 2000000
#define E_DIR 4000000

#define SCAN_BLK 1024
#define N_SCAN_BLOCKS ((N_NODES + SCAN_BLK - 1) / SCAN_BLK)   // 147

// ---------------- scratch (device globals; no runtime allocation) ------------
__device__ __align__(16) float d_deg[N_NODES];
__device__ __align__(16) float d_dinv[N_NODES];
__device__ __align__(16) int   d_cnt[N_NODES];
__device__ __align__(16) int   d_rowptr[N_NODES + 1];
__device__ __align__(16) int   d_wp[N_NODES];
__device__ __align__(16) int   d_partials[N_SCAN_BLOCKS];
__device__ __align__(16) int   d_col[E_DIR];
__device__ __align__(16) float d_w[E_DIR];
__device__ __align__(16) float d_e0[NH];
__device__ __align__(16) float d_e1[NH];
__device__ __align__(16) float d_acc[NH];
__device__ int d_is64;

// ---------------- dtype-robust index read (parallel detect) -------------------
// JAX default config downcasts int64 -> int32; edge arrays may be either.
// 256 threads each validate one int64 candidate; any out-of-range => int32.
__global__ void detect_kernel(const void* __restrict__ p) {
    __shared__ int bad;
    if (threadIdx.x == 0) bad = 0;
    __syncthreads();
    const long long* q = (const long long*)p;
    long long v = q[threadIdx.x];
    if (v < 0 || v >= N_NODES) bad = 1;
    __syncthreads();
    if (threadIdx.x == 0) d_is64 = bad ? 0 : 1;
}

__device__ __forceinline__ int get_idx(const void* __restrict__ p, int k) {
    if (d_is64) return (int)((const long long*)p)[k];
    return ((const int*)p)[k];
}

// ---------------- build phase -------------------------------------------------

__global__ void zero_kernel() {
    int i = blockIdx.x * blockDim.x + threadIdx.x;
    if (i < N_NODES) { d_deg[i] = 0.0f; d_cnt[i] = 0; }
}

__global__ void deg_kernel(const void* __restrict__ eu,
                           const void* __restrict__ ei,
                           const float* __restrict__ ev) {
    int k = blockIdx.x * blockDim.x + threadIdx.x;
    if (k >= E_IN) return;
    int u  = get_idx(eu, k);
    int it = get_idx(ei, k);
    if ((unsigned)u >= U_NODES || (unsigned)it >= I_NODES) return;  // safety
    it += U_NODES;
    float v = ev[k];
    atomicAdd(&d_deg[u], v);
    atomicAdd(&d_deg[it], v);
    atomicAdd(&d_cnt[u], 1);
    atomicAdd(&d_cnt[it], 1);
}

__global__ void dinv_kernel() {
    int i = blockIdx.x * blockDim.x + threadIdx.x;
    if (i >= N_NODES) return;
    float dg = d_deg[i];
    d_dinv[i] = (dg > 0.0f) ? rsqrtf(fmaxf(dg, 1e-12f)) : 0.0f;
}

__global__ void scan1_kernel() {
    __shared__ int sh[SCAN_BLK];
    int t = threadIdx.x;
    int idx = blockIdx.x * SCAN_BLK + t;
    int v = (idx < N_NODES) ? d_cnt[idx] : 0;
    sh[t] = v;
    __syncthreads();
    for (int off = 1; off < SCAN_BLK; off <<= 1) {
        int x = (t >= off) ? sh[t - off] : 0;
        __syncthreads();
        sh[t] += x;
        __syncthreads();
    }
    if (idx < N_NODES) d_rowptr[idx] = sh[t] - v;   // block-local exclusive
    if (t == SCAN_BLK - 1) d_partials[blockIdx.x] = sh[t];
}

// parallel exclusive scan of the 147 block sums (one 256-thread block)
__global__ void scan2_kernel() {
    __shared__ int sh[256];
    int t = threadIdx.x;
    int v = (t < N_SCAN_BLOCKS) ? d_partials[t] : 0;
    sh[t] = v;
    __syncthreads();
    for (int off = 1; off < 256; off <<= 1) {
        int x = (t >= off) ? sh[t - off] : 0;
        __syncthreads();
        sh[t] += x;
        __syncthreads();
    }
    if (t < N_SCAN_BLOCKS) d_partials[t] = sh[t] - v;   // exclusive
}

__global__ void scan3_kernel() {
    int idx = blockIdx.x * blockDim.x + threadIdx.x;
    if (idx < N_NODES) {
        int rp = d_rowptr[idx] + d_partials[idx >> 10];
        d_rowptr[idx] = rp;
        d_wp[idx] = rp;
    }
    if (idx == 0) d_rowptr[N_NODES] = E_DIR;
}

__global__ void scatter_kernel(const void* __restrict__ eu,
                               const void* __restrict__ ei,
                               const float* __restrict__ ev) {
    int k = blockIdx.x * blockDim.x + threadIdx.x;
    if (k >= E_IN) return;
    int u  = get_idx(eu, k);
    int it = get_idx(ei, k);
    if ((unsigned)u >= U_NODES || (unsigned)it >= I_NODES) return;  // safety
    it += U_NODES;
    float v = ev[k];
    float w = d_dinv[u] * v * d_dinv[it];   // symmetric weight
    int p0 = atomicAdd(&d_wp[u], 1);
    d_col[p0] = it;
    d_w[p0]   = w;
    int p1 = atomicAdd(&d_wp[it], 1);
    d_col[p1] = u;
    d_w[p1]   = w;
}

// e0 = acc = concat(emb_users, emb_items), float4 vectorized (UH % 4 == 0)
__global__ void init_e_kernel(const float* __restrict__ emb_u,
                              const float* __restrict__ emb_i) {
    int q = blockIdx.x * blockDim.x + threadIdx.x;   // float4 index
    if (q >= NH / 4) return;
    int i = q * 4;
    float4 v = (i < UH) ? ((const float4*)emb_u)[q]
                        : ((const float4*)emb_i)[q - UH / 4];
    ((float4*)d_e0)[q]  = v;
    ((float4*)d_acc)[q] = v;
}

// ---------------- propagation layers ------------------------------------------
// R4-champion structure: one warp per row, lane l holds dims [2l,2l+1],
// per edge: scalar col + w broadcast loads + whole-warp float2 row gather,
// unrolled x4, fp32 acc RMW in-kernel.

__global__ void layer_kernel(int flip) {
    const float* __restrict__ ein  = flip ? d_e1 : d_e0;
    float*       __restrict__ eout = flip ? d_e0 : d_e1;
    int warp = (blockIdx.x * blockDim.x + threadIdx.x) >> 5;
    int lane = threadIdx.x & 31;
    if (warp >= N_NODES) return;
    int s = d_rowptr[warp];
    int e = d_rowptr[warp + 1];
    float2 sum = make_float2(0.0f, 0.0f);
    int base = lane * 2;
    int j = s;
    for (; j + 3 < e; j += 4) {          // unrolled x4 for MLP
        int   c0 = d_col[j],     c1 = d_col[j + 1];
        int   c2 = d_col[j + 2], c3 = d_col[j + 3];
        float w0 = d_w[j],       w1 = d_w[j + 1];
        float w2 = d_w[j + 2],   w3 = d_w[j + 3];
        float2 v0 = *(const float2*)(ein + (size_t)c0 * H + base);
        float2 v1 = *(const float2*)(ein + (size_t)c1 * H + base);
        float2 v2 = *(const float2*)(ein + (size_t)c2 * H + base);
        float2 v3 = *(const float2*)(ein + (size_t)c3 * H + base);
        sum.x += w0 * v0.x + w1 * v1.x + w2 * v2.x + w3 * v3.x;
        sum.y += w0 * v0.y + w1 * v1.y + w2 * v2.y + w3 * v3.y;
    }
    for (; j < e; j++) {
        int c = d_col[j];
        float w = d_w[j];
        float2 v = *(const float2*)(ein + (size_t)c * H + base);
        sum.x += w * v.x;
        sum.y += w * v.y;
    }
    size_t o = (size_t)warp * H + base;
    *(float2*)(eout + o) = sum;
    float2* ap = (float2*)(d_acc + o);
    float2 a = *ap;
    a.x += sum.x;
    a.y += sum.y;
    *ap = a;
}

// ---------------- epilogue -----------------------------------------------------
// out = [acc_users/25 | emb_users | acc_items/25 | emb_items], float4 path.
__global__ void final_kernel(const float* __restrict__ emb_u,
                             const float* __restrict__ emb_i,
                             float* __restrict__ out, int out_n) {
    const float sc = 1.0f / 25.0f;   // alpha * 1/(L+1) = 1/5 * 1/5
    int q = blockIdx.x * blockDim.x + threadIdx.x;   // float4 index
    int i = q * 4;
    if (i >= out_n) return;
    if (i + 3 < out_n && i + 4 <= 2 * UH + 2 * IH) {
        float4 v;
        if (i < UH) {
            float4 a = ((const float4*)d_acc)[q];
            v = make_float4(a.x * sc, a.y * sc, a.z * sc, a.w * sc);
        } else if (i < 2 * UH) {
            v = ((const float4*)emb_u)[q - UH / 4];
        } else if (i < 2 * UH + IH) {
            float4 a = ((const float4*)d_acc)[UH / 4 + (q - 2 * UH / 4)];
            v = make_float4(a.x * sc, a.y * sc, a.z * sc, a.w * sc);
        } else {
            v = ((const float4*)emb_i)[q - (2 * UH + IH) / 4];
        }
        ((float4*)out)[q] = v;
    } else {
        for (int t = i; t < out_n && t < i + 4; t++) {
            float v;
            if (t < UH)                   v = d_acc[t] * sc;
            else if (t < 2 * UH)          v = emb_u[t - UH];
            else if (t < 2 * UH + IH)     v = d_acc[UH + (t - 2 * UH)] * sc;
            else if (t < 2 * UH + 2 * IH) v = emb_i[t - 2 * UH - IH];
            else                          v = 0.0f;
            out[t] = v;
        }
    }
}

// ---------------- launch ------------------------------------------------------

extern "C" void kernel_launch(void* const* d_in, const int* in_sizes, int n_in,
                              void* d_out, int out_size) {
    const float* emb_u = (const float*)d_in[0];
    const float* emb_i = (const float*)d_in[1];
    const void*  eu    = d_in[2];
    const void*  ei    = d_in[3];
    const float* ev    = (const float*)d_in[4];
    float* out = (float*)d_out;

    const int TB = 256;
    int gb_nodes = (N_NODES + TB - 1) / TB;
    int gb_edges = (E_IN + TB - 1) / TB;
    int gb_nh4   = (NH / 4 + TB - 1) / TB;
    int gb_out4  = (out_size / 4 + TB) / TB;

    detect_kernel<<<1, 256>>>(eu);
    zero_kernel<<<gb_nodes, TB>>>();
    deg_kernel<<<gb_edges, TB>>>(eu, ei, ev);
    dinv_kernel<<<gb_nodes, TB>>>();
    scan1_kernel<<<N_SCAN_BLOCKS, SCAN_BLK>>>();
    scan2_kernel<<<1, 256>>>();
    scan3_kernel<<<gb_nodes, TB>>>();
    scatter_kernel<<<gb_edges, TB>>>(eu, ei, ev);
    init_e_kernel<<<gb_nh4, TB>>>(emb_u, emb_i);

    // warp per row, TB=64 (2 warps/block): continue the winning TB axis
    const int LTB = 64;
    int layer_blocks = (N_NODES * 32 + LTB - 1) / LTB;
    layer_kernel<<<layer_blocks, LTB>>>(0);   // e0 -> e1
    layer_kernel<<<layer_blocks, LTB>>>(1);   // e1 -> e0
    layer_kernel<<<layer_blocks, LTB>>>(0);   // e0 -> e1
    layer_kernel<<<layer_blocks, LTB>>>(1);   // e1 -> e0

    final_kernel<<<gb_out4, TB>>>(emb_u, emb_i, out, out_size);
}

// round 13
// speedup vs baseline: 1.3945x; 1.0255x over previous
#include <cuda_runtime.h>
#include <stdint.h>

#define U_NODES 100000
#define I_NODES 50000
#define N_NODES 150000
#define H 64
#define UH (U_NODES * H)       // 6,400,000
#define IH (I_NODES * H)       // 3,200,000
#define NH (N_NODES * H)       // 9,600,000
#define E_IN 2000000
#define E_DIR 4000000

#define SCAN_BLK 1024
#define N_SCAN_BLOCKS ((N_NODES + SCAN_BLK - 1) / SCAN_BLK)   // 147

// ---------------- scratch (device globals; no runtime allocation) ------------
__device__ __align__(16) float d_deg[N_NODES];
__device__ __align__(16) float d_dinv[N_NODES];
__device__ __align__(16) int   d_cnt[N_NODES];
__device__ __align__(16) int   d_rowptr[N_NODES + 1];
__device__ __align__(16) int   d_wp[N_NODES];
__device__ __align__(16) int   d_partials[N_SCAN_BLOCKS];
__device__ __align__(16) int   d_col[E_DIR];
__device__ __align__(16) float d_w[E_DIR];
__device__ __align__(16) float d_e0[NH];
__device__ __align__(16) float d_e1[NH];
__device__ __align__(16) float d_acc[NH];
__device__ int d_is64;
__device__ int d_allones;

// ---------------- kernels ----------------------------------------------------

// zero node scratch; reset flags (thread 0)
__global__ void zero_kernel() {
    int i = blockIdx.x * blockDim.x + threadIdx.x;
    if (i == 0) d_allones = 1;
    if (i < N_NODES) { d_deg[i] = 0.0f; d_cnt[i] = 0; }
}

// Combined probe: block 0 detects edge-index dtype (JAX default config
// downcasts int64 -> int32, so arrays may be either); all blocks check
// whether every edge value is exactly 1.0f (full 2M-element scan).
__global__ void probe_kernel(const void* __restrict__ eu,
                             const float* __restrict__ ev) {
    int k = blockIdx.x * blockDim.x + threadIdx.x;
    if (blockIdx.x == 0) {
        __shared__ int bad;
        if (threadIdx.x == 0) bad = 0;
        __syncthreads();
        const long long* q = (const long long*)eu;
        long long v = q[threadIdx.x];
        if (v < 0 || v >= N_NODES) bad = 1;
        __syncthreads();
        if (threadIdx.x == 0) d_is64 = bad ? 0 : 1;
    }
    // all-ones check over the full value array
    bool ok = true;
    for (int t = k; t < E_IN; t += gridDim.x * blockDim.x)
        if (ev[t] != 1.0f) ok = false;
    if (!ok) d_allones = 0;
}

__device__ __forceinline__ int get_idx(const void* __restrict__ p, int k) {
    if (d_is64) return (int)((const long long*)p)[k];
    return ((const int*)p)[k];
}

// degree/count accumulation; float atomics skipped when all values are 1.0
__global__ void deg_kernel(const void* __restrict__ eu,
                           const void* __restrict__ ei,
                           const float* __restrict__ ev) {
    int k = blockIdx.x * blockDim.x + threadIdx.x;
    if (k >= E_IN) return;
    int u  = get_idx(eu, k);
    int it = get_idx(ei, k);
    if ((unsigned)u >= U_NODES || (unsigned)it >= I_NODES) return;  // safety
    it += U_NODES;
    atomicAdd(&d_cnt[u], 1);
    atomicAdd(&d_cnt[it], 1);
    if (!d_allones) {
        float v = ev[k];
        atomicAdd(&d_deg[u], v);
        atomicAdd(&d_deg[it], v);
    }
}

// block-level exclusive scan of counts (+ fused dinv computation)
__global__ void scan1_kernel() {
    __shared__ int sh[SCAN_BLK];
    int t = threadIdx.x;
    int idx = blockIdx.x * SCAN_BLK + t;
    int v = (idx < N_NODES) ? d_cnt[idx] : 0;
    // fused dinv: deg == cnt when all values are 1.0 ((float)cnt exact < 2^24)
    if (idx < N_NODES) {
        float dg = d_allones ? (float)v : d_deg[idx];
        d_dinv[idx] = (dg > 0.0f) ? rsqrtf(fmaxf(dg, 1e-12f)) : 0.0f;
    }
    sh[t] = v;
    __syncthreads();
    for (int off = 1; off < SCAN_BLK; off <<= 1) {
        int x = (t >= off) ? sh[t - off] : 0;
        __syncthreads();
        sh[t] += x;
        __syncthreads();
    }
    if (idx < N_NODES) d_rowptr[idx] = sh[t] - v;   // block-local exclusive
    if (t == SCAN_BLK - 1) d_partials[blockIdx.x] = sh[t];
}

// parallel exclusive scan of the 147 block sums (one 256-thread block)
__global__ void scan2_kernel() {
    __shared__ int sh[256];
    int t = threadIdx.x;
    int v = (t < N_SCAN_BLOCKS) ? d_partials[t] : 0;
    sh[t] = v;
    __syncthreads();
    for (int off = 1; off < 256; off <<= 1) {
        int x = (t >= off) ? sh[t - off] : 0;
        __syncthreads();
        sh[t] += x;
        __syncthreads();
    }
    if (t < N_SCAN_BLOCKS) d_partials[t] = sh[t] - v;   // exclusive
}

__global__ void scan3_kernel() {
    int idx = blockIdx.x * blockDim.x + threadIdx.x;
    if (idx < N_NODES) {
        int rp = d_rowptr[idx] + d_partials[idx >> 10];
        d_rowptr[idx] = rp;
        d_wp[idx] = rp;
    }
    if (idx == 0) d_rowptr[N_NODES] = E_DIR;
}

__global__ void scatter_kernel(const void* __restrict__ eu,
                               const void* __restrict__ ei,
                               const float* __restrict__ ev) {
    int k = blockIdx.x * blockDim.x + threadIdx.x;
    if (k >= E_IN) return;
    int u  = get_idx(eu, k);
    int it = get_idx(ei, k);
    if ((unsigned)u >= U_NODES || (unsigned)it >= I_NODES) return;  // safety
    it += U_NODES;
    float v = d_allones ? 1.0f : ev[k];
    float w = d_dinv[u] * v * d_dinv[it];   // symmetric weight
    int p0 = atomicAdd(&d_wp[u], 1);
    d_col[p0] = it;
    d_w[p0]   = w;
    int p1 = atomicAdd(&d_wp[it], 1);
    d_col[p1] = u;
    d_w[p1]   = w;
}

// e0 = acc = concat(emb_users, emb_items), float4 vectorized (UH % 4 == 0)
__global__ void init_e_kernel(const float* __restrict__ emb_u,
                              const float* __restrict__ emb_i) {
    int q = blockIdx.x * blockDim.x + threadIdx.x;   // float4 index
    if (q >= NH / 4) return;
    int i = q * 4;
    float4 v = (i < UH) ? ((const float4*)emb_u)[q]
                        : ((const float4*)emb_i)[q - UH / 4];
    ((float4*)d_e0)[q]  = v;
    ((float4*)d_acc)[q] = v;
}

// ---------------- propagation layers ------------------------------------------
// Converged champion structure: one warp per row, lane l holds dims [2l,2l+1],
// per edge: scalar col + w broadcast loads + whole-warp float2 row gather,
// unrolled x4, fp32 acc RMW in-kernel. TB=64.

__global__ void layer_kernel(int flip) {
    const float* __restrict__ ein  = flip ? d_e1 : d_e0;
    float*       __restrict__ eout = flip ? d_e0 : d_e1;
    int warp = (blockIdx.x * blockDim.x + threadIdx.x) >> 5;
    int lane = threadIdx.x & 31;
    if (warp >= N_NODES) return;
    int s = d_rowptr[warp];
    int e = d_rowptr[warp + 1];
    float2 sum = make_float2(0.0f, 0.0f);
    int base = lane * 2;
    int j = s;
    for (; j + 3 < e; j += 4) {          // unrolled x4 for MLP
        int   c0 = d_col[j],     c1 = d_col[j + 1];
        int   c2 = d_col[j + 2], c3 = d_col[j + 3];
        float w0 = d_w[j],       w1 = d_w[j + 1];
        float w2 = d_w[j + 2],   w3 = d_w[j + 3];
        float2 v0 = *(const float2*)(ein + (size_t)c0 * H + base);
        float2 v1 = *(const float2*)(ein + (size_t)c1 * H + base);
        float2 v2 = *(const float2*)(ein + (size_t)c2 * H + base);
        float2 v3 = *(const float2*)(ein + (size_t)c3 * H + base);
        sum.x += w0 * v0.x + w1 * v1.x + w2 * v2.x + w3 * v3.x;
        sum.y += w0 * v0.y + w1 * v1.y + w2 * v2.y + w3 * v3.y;
    }
    for (; j < e; j++) {
        int c = d_col[j];
        float w = d_w[j];
        float2 v = *(const float2*)(ein + (size_t)c * H + base);
        sum.x += w * v.x;
        sum.y += w * v.y;
    }
    size_t o = (size_t)warp * H + base;
    *(float2*)(eout + o) = sum;
    float2* ap = (float2*)(d_acc + o);
    float2 a = *ap;
    a.x += sum.x;
    a.y += sum.y;
    *ap = a;
}

// ---------------- epilogue -----------------------------------------------------
// out = [acc_users/25 | emb_users | acc_items/25 | emb_items], float4 path.
__global__ void final_kernel(const float* __restrict__ emb_u,
                             const float* __restrict__ emb_i,
                             float* __restrict__ out, int out_n) {
    const float sc = 1.0f / 25.0f;   // alpha * 1/(L+1) = 1/5 * 1/5
    int q = blockIdx.x * blockDim.x + threadIdx.x;   // float4 index
    int i = q * 4;
    if (i >= out_n) return;
    if (i + 3 < out_n && i + 4 <= 2 * UH + 2 * IH) {
        float4 v;
        if (i < UH) {
            float4 a = ((const float4*)d_acc)[q];
            v = make_float4(a.x * sc, a.y * sc, a.z * sc, a.w * sc);
        } else if (i < 2 * UH) {
            v = ((const float4*)emb_u)[q - UH / 4];
        } else if (i < 2 * UH + IH) {
            float4 a = ((const float4*)d_acc)[UH / 4 + (q - 2 * UH / 4)];
            v = make_float4(a.x * sc, a.y * sc, a.z * sc, a.w * sc);
        } else {
            v = ((const float4*)emb_i)[q - (2 * UH + IH) / 4];
        }
        ((float4*)out)[q] = v;
    } else {
        for (int t = i; t < out_n && t < i + 4; t++) {
            float v;
            if (t < UH)                   v = d_acc[t] * sc;
            else if (t < 2 * UH)          v = emb_u[t - UH];
            else if (t < 2 * UH + IH)     v = d_acc[UH + (t - 2 * UH)] * sc;
            else if (t < 2 * UH + 2 * IH) v = emb_i[t - 2 * UH - IH];
            else                          v = 0.0f;
            out[t] = v;
        }
    }
}

// ---------------- launch ------------------------------------------------------

extern "C" void kernel_launch(void* const* d_in, const int* in_sizes, int n_in,
                              void* d_out, int out_size) {
    const float* emb_u = (const float*)d_in[0];
    const float* emb_i = (const float*)d_in[1];
    const void*  eu    = d_in[2];
    const void*  ei    = d_in[3];
    const float* ev    = (const float*)d_in[4];
    float* out = (float*)d_out;

    const int TB = 256;
    int gb_nodes = (N_NODES + TB - 1) / TB;
    int gb_edges = (E_IN + TB - 1) / TB;
    int gb_nh4   = (NH / 4 + TB - 1) / TB;
    int gb_out4  = (out_size / 4 + TB) / TB;

    zero_kernel<<<gb_nodes, TB>>>();          // also resets d_allones
    probe_kernel<<<592, TB>>>(eu, ev);        // dtype + all-ones (full scan)
    deg_kernel<<<gb_edges, TB>>>(eu, ei, ev);
    scan1_kernel<<<N_SCAN_BLOCKS, SCAN_BLK>>>();   // fused dinv
    scan2_kernel<<<1, 256>>>();
    scan3_kernel<<<gb_nodes, TB>>>();
    scatter_kernel<<<gb_edges, TB>>>(eu, ei, ev);
    init_e_kernel<<<gb_nh4, TB>>>(emb_u, emb_i);

    const int LTB = 64;                       // champion layer config
    int layer_blocks = (N_NODES * 32 + LTB - 1) / LTB;
    layer_kernel<<<layer_blocks, LTB>>>(0);   // e0 -> e1
    layer_kernel<<<layer_blocks, LTB>>>(1);   // e1 -> e0
    layer_kernel<<<layer_blocks, LTB>>>(0);   // e0 -> e1
    layer_kernel<<<layer_blocks, LTB>>>(1);   // e1 -> e0

    final_kernel<<<gb_out4, TB>>>(emb_u, emb_i, out, out_size);
}